// round 3
// baseline (speedup 1.0000x reference)
#include <cuda_runtime.h>

#define SEQ   2048
#define NX    768
#define NH    12
#define HD    64
#define BSZ   2
#define MROWS (BSZ*SEQ)

#define BQ 128
#define BK 64
// Qs[BQ][64] + Ks[BK][65] + Vs[BK][65] + Ps[BQ][65]
#define FLASH_SMEM ((BQ*HD + BK*(HD+1) + BK*(HD+1) + BQ*(BK+1))*4)

// Scratch (allocation-free rule: __device__ globals). 4 x 12.6 MB.
__device__ float g_q[(size_t)BSZ*SEQ*NX];
__device__ float g_k[(size_t)BSZ*SEQ*NX];
__device__ float g_v[(size_t)BSZ*SEQ*NX];
__device__ float g_att[(size_t)BSZ*SEQ*NX];

// ---------------------------------------------------------------------------
// 128x128x8 SGEMM, 256 threads, 8x8 per-thread microtile.
// mode 1: C = A@B + bias, split columns [0,768)->g_q, [768,1536)->g_k, rest->g_v
// mode 2: A := g_att (attention output), C = d_out
// ---------------------------------------------------------------------------
__global__ __launch_bounds__(256, 2)
void sgemm_kernel(const float* __restrict__ A, const float* __restrict__ B,
                  const float* __restrict__ bias, float* __restrict__ C,
                  int M, int N, int K, int mode)
{
    __shared__ float As[8][128];   // transposed A tile: As[k][m]
    __shared__ float Bs[8][128];

    const float* Ap = (mode == 2) ? g_att : A;
    const int tid = threadIdx.x;
    const int m0 = blockIdx.y * 128;
    const int n0 = blockIdx.x * 128;
    const int ty = tid >> 4, tx = tid & 15;

    const int a_row  = tid >> 1;          // 0..127
    const int a_part = (tid & 1) * 4;     // 0 or 4
    const int b_row  = tid >> 5;          // 0..7
    const int b_col  = (tid & 31) * 4;    // 0..124

    float acc[8][8];
#pragma unroll
    for (int i = 0; i < 8; i++)
#pragma unroll
        for (int j = 0; j < 8; j++) acc[i][j] = 0.f;

    for (int k0 = 0; k0 < K; k0 += 8) {
        float4 a4 = *(const float4*)(Ap + (size_t)(m0 + a_row) * K + k0 + a_part);
        As[a_part + 0][a_row] = a4.x;
        As[a_part + 1][a_row] = a4.y;
        As[a_part + 2][a_row] = a4.z;
        As[a_part + 3][a_row] = a4.w;
        *(float4*)(&Bs[b_row][b_col]) =
            *(const float4*)(B + (size_t)(k0 + b_row) * N + n0 + b_col);
        __syncthreads();

#pragma unroll
        for (int kk = 0; kk < 8; kk++) {
            float ar[8], br[8];
            *(float4*)(ar)     = *(const float4*)(&As[kk][ty * 8]);
            *(float4*)(ar + 4) = *(const float4*)(&As[kk][ty * 8 + 4]);
            *(float4*)(br)     = *(const float4*)(&Bs[kk][tx * 8]);
            *(float4*)(br + 4) = *(const float4*)(&Bs[kk][tx * 8 + 4]);
#pragma unroll
            for (int i = 0; i < 8; i++)
#pragma unroll
                for (int j = 0; j < 8; j++)
                    acc[i][j] = fmaf(ar[i], br[j], acc[i][j]);
        }
        __syncthreads();
    }

    if (mode == 1) {
        // 768 % 128 == 0 -> whole 128-col tile maps to one of q/k/v
        const int which = n0 / NX;
        float* dst = (which == 0) ? g_q : (which == 1) ? g_k : g_v;
        const int nn0 = n0 - which * NX;
#pragma unroll
        for (int i = 0; i < 8; i++) {
            const int r = m0 + ty * 8 + i;
#pragma unroll
            for (int j = 0; j < 8; j++) {
                const int c = tx * 8 + j;
                dst[(size_t)r * NX + nn0 + c] = acc[i][j] + bias[n0 + c];
            }
        }
    } else {
#pragma unroll
        for (int i = 0; i < 8; i++) {
            const int r = m0 + ty * 8 + i;
#pragma unroll
            for (int j = 0; j < 8; j++) {
                const int c = n0 + tx * 8 + j;
                C[(size_t)r * N + c] = acc[i][j] + bias[c];
            }
        }
    }
}

// ---------------------------------------------------------------------------
// Flash attention, fp32. One CTA per (q-tile of 128, head, batch).
// Per head, Q/K/V are contiguous [2048,64] thanks to the GPT-2 "faithful
// reshape" (head h block = offset h*SEQ*HD inside the extracted buffer).
// Masked entries use the exact reference bias: -10000 + attention_mask[k];
// exp(-10000 - m) == 0 in fp32, so truncating the k loop at the causal
// boundary is bit-identical to the full-row softmax.
// Thread map: ty=tid/16 owns 8 q-rows, tx=tid%16 owns 4 k-cols (S phase)
// and 4 d-cols (PV phase). Row reductions via half-warp shfl_xor.
// ---------------------------------------------------------------------------
__global__ __launch_bounds__(256, 2)
void flash_kernel(const float* __restrict__ am_g)
{
    extern __shared__ float sm[];
    float* Qs = sm;                           // [BQ][HD]
    float* Ks = Qs + BQ * HD;                 // [BK][HD+1]
    float* Vs = Ks + BK * (HD + 1);           // [BK][HD+1]
    float* Ps = Vs + BK * (HD + 1);           // [BQ][BK+1]

    const int tid = threadIdx.x;
    const int qt = blockIdx.x, h = blockIdx.y, b = blockIdx.z;
    const size_t headoff = (size_t)b * SEQ * NX + (size_t)h * SEQ * HD;
    const float* Qh = g_q + headoff;
    const float* Kh = g_k + headoff;
    const float* Vh = g_v + headoff;
    const float* am = am_g + (size_t)b * SEQ;
    const int q0 = qt * BQ;

    // Load Q tile (reused across all k tiles)
    for (int idx = tid; idx < BQ * (HD / 4); idx += 256) {
        const int row = idx >> 4;
        const int c4  = (idx & 15) * 4;
        *(float4*)(Qs + row * HD + c4) =
            *(const float4*)(Qh + (size_t)(q0 + row) * HD + c4);
    }

    const int ty = tid >> 4, tx = tid & 15;
    const int qr0 = ty * 8, kc0 = tx * 4;

    float m_i[8], l_i[8], O[8][4];
#pragma unroll
    for (int i = 0; i < 8; i++) {
        m_i[i] = -1e30f; l_i[i] = 0.f;
#pragma unroll
        for (int j = 0; j < 4; j++) O[i][j] = 0.f;
    }

    const int ktmax = 2 * qt + 1;   // last tile touching the causal diagonal
    for (int kt = 0; kt <= ktmax; kt++) {
        __syncthreads();            // prev iteration's PV reads of Vs/Ps done
        const int k0 = kt * BK;
        for (int idx = tid; idx < BK * (HD / 4); idx += 256) {
            const int row = idx >> 4;
            const int c4  = (idx & 15) * 4;
            float4 kv = *(const float4*)(Kh + (size_t)(k0 + row) * HD + c4);
            float4 vv = *(const float4*)(Vh + (size_t)(k0 + row) * HD + c4);
            float* kd = Ks + row * (HD + 1) + c4;
            kd[0] = kv.x; kd[1] = kv.y; kd[2] = kv.z; kd[3] = kv.w;
            float* vd = Vs + row * (HD + 1) + c4;
            vd[0] = vv.x; vd[1] = vv.y; vd[2] = vv.z; vd[3] = vv.w;
        }
        __syncthreads();

        // S = Q @ K^T for my 8x4 sub-tile
        float s[8][4];
#pragma unroll
        for (int i = 0; i < 8; i++)
#pragma unroll
            for (int j = 0; j < 4; j++) s[i][j] = 0.f;

#pragma unroll 4
        for (int d = 0; d < HD; d++) {
            float kr[4];
#pragma unroll
            for (int j = 0; j < 4; j++) kr[j] = Ks[(kc0 + j) * (HD + 1) + d];
#pragma unroll
            for (int i = 0; i < 8; i++) {
                const float qv = Qs[(qr0 + i) * HD + d];
#pragma unroll
                for (int j = 0; j < 4; j++) s[i][j] = fmaf(qv, kr[j], s[i][j]);
            }
        }

        float amr[4];
#pragma unroll
        for (int j = 0; j < 4; j++) amr[j] = am[k0 + kc0 + j];

        // scale + causal bias + attention_mask, exactly as reference:
        // valid:  w*0.125 + am ; masked: -10000 + am
#pragma unroll
        for (int i = 0; i < 8; i++) {
            const int qg = q0 + qr0 + i;
#pragma unroll
            for (int j = 0; j < 4; j++) {
                const int kg = k0 + kc0 + j;
                s[i][j] = (kg <= qg) ? fmaf(s[i][j], 0.125f, amr[j])
                                     : (-10000.0f + amr[j]);
            }
        }

        // Online softmax per q-row (shared by the 16 tx lanes = half warp)
#pragma unroll
        for (int i = 0; i < 8; i++) {
            float tm = fmaxf(fmaxf(s[i][0], s[i][1]), fmaxf(s[i][2], s[i][3]));
#pragma unroll
            for (int off = 8; off >= 1; off >>= 1)
                tm = fmaxf(tm, __shfl_xor_sync(0xffffffffu, tm, off));
            const float mn = fmaxf(m_i[i], tm);
            const float corr = __expf(m_i[i] - mn);
            m_i[i] = mn;
            float rs = 0.f;
#pragma unroll
            for (int j = 0; j < 4; j++) {
                const float p = __expf(s[i][j] - mn);
                s[i][j] = p;
                rs += p;
            }
#pragma unroll
            for (int off = 8; off >= 1; off >>= 1)
                rs += __shfl_xor_sync(0xffffffffu, rs, off);
            l_i[i] = l_i[i] * corr + rs;
#pragma unroll
            for (int j = 0; j < 4; j++) O[i][j] *= corr;
            float* pd = Ps + (qr0 + i) * (BK + 1) + kc0;
#pragma unroll
            for (int j = 0; j < 4; j++) pd[j] = s[i][j];
        }
        __syncthreads();

        // O += P @ V  (tx now indexes 4 d-columns)
#pragma unroll 4
        for (int k = 0; k < BK; k++) {
            float vr[4];
#pragma unroll
            for (int j = 0; j < 4; j++) vr[j] = Vs[k * (HD + 1) + kc0 + j];
#pragma unroll
            for (int i = 0; i < 8; i++) {
                const float p = Ps[(qr0 + i) * (BK + 1) + k];
#pragma unroll
                for (int j = 0; j < 4; j++) O[i][j] = fmaf(p, vr[j], O[i][j]);
            }
        }
    }

    // Normalize and write to merged [bs, s2, h*64+d] layout for the proj GEMM
#pragma unroll
    for (int i = 0; i < 8; i++) {
        const float inv = 1.0f / l_i[i];
        const int qg = q0 + qr0 + i;
        float4 o4;
        o4.x = O[i][0] * inv; o4.y = O[i][1] * inv;
        o4.z = O[i][2] * inv; o4.w = O[i][3] * inv;
        *(float4*)(g_att + ((size_t)b * SEQ + qg) * NX + h * HD + kc0) = o4;
    }
}

// ---------------------------------------------------------------------------
extern "C" void kernel_launch(void* const* d_in, const int* in_sizes, int n_in,
                              void* d_out, int out_size)
{
    const float* hidden = (const float*)d_in[0];
    const float* amask  = (const float*)d_in[1];
    const float* w_attn = (const float*)d_in[2];
    const float* b_attn = (const float*)d_in[3];
    const float* w_proj = (const float*)d_in[4];
    const float* b_proj = (const float*)d_in[5];
    float* out = (float*)d_out;

    // >48KB dynamic smem opt-in (not a stream op; capture-safe, idempotent)
    cudaFuncSetAttribute(flash_kernel,
                         cudaFuncAttributeMaxDynamicSharedMemorySize, FLASH_SMEM);

    // 1) QKV projection: [4096,768] @ [768,2304] + b, split into g_q/g_k/g_v
    sgemm_kernel<<<dim3(3 * NX / 128, MROWS / 128), 256>>>(
        hidden, w_attn, b_attn, nullptr, MROWS, 3 * NX, NX, 1);

    // 2) Causal attention per (b, head), flash-style
    flash_kernel<<<dim3(SEQ / BQ, NH, BSZ), 256, FLASH_SMEM>>>(amask);

    // 3) Output projection: g_att [4096,768] @ [768,768] + b -> d_out
    sgemm_kernel<<<dim3(NX / 128, MROWS / 128), 256>>>(
        nullptr, w_proj, b_proj, out, MROWS, NX, NX, 2);
}